// round 17
// baseline (speedup 1.0000x reference)
#include <cuda_runtime.h>
#include <cuda_bf16.h>
#include <cstdint>

// Problem dims: B=1, S=256, N=512, C_M=64, C_Z=128, H=8, C_H=32  (H*C_H = 256)
//
// Pipeline (tf32 tensor-core GEMMs):
//   k_mproj   : FUSED LN(m) + tf32 MMA @ [Wm;Wg]^T  -> d_V [h][t][j] (transposed), d_G [r][256]
//   k_zpath   : LN(z) . Wz[h] + mask bias           -> d_W logits
//   k_softmax : row softmax, tf32-rounded           -> d_W in place
//   k_gemm    : tf32 MMA, 2 CTAs/SM + cp.async (R15 measured-good: 241us) -> d_O
//   k_out     : tf32 MMA: (G .* O) @ Wo^T           -> out [s][i][64]
// k_gemm sits at launch slot 4 -> captured by the profiler next round.

// ---------------- scratch ----------------
__device__ float d_V [8 * 8192 * 512];       // [h][t=s*32+e][j]  tf32-rounded
__device__ float d_G [131072 * 256];
__device__ float d_W [8 * 512 * 512];        // tf32-rounded softmax weights
__device__ float d_O [512 * 256 * 256];

__inline__ __device__ float warpSum(float v) {
    #pragma unroll
    for (int o = 16; o > 0; o >>= 1) v += __shfl_xor_sync(0xffffffffu, v, o);
    return v;
}
__inline__ __device__ float warpMax(float v) {
    #pragma unroll
    for (int o = 16; o > 0; o >>= 1) v = fmaxf(v, __shfl_xor_sync(0xffffffffu, v, o));
    return v;
}
__inline__ __device__ float to_tf32(float x) {
    uint32_t u;
    asm("cvt.rna.tf32.f32 %0, %1;" : "=r"(u) : "f"(x));
    return __uint_as_float(u);
}
#define MMA_TF32(acc, af, bf)                                             \
    asm volatile(                                                         \
        "mma.sync.aligned.m16n8k8.row.col.f32.tf32.tf32.f32 "             \
        "{%0,%1,%2,%3}, {%4,%5,%6,%7}, {%8,%9}, {%0,%1,%2,%3};\n"         \
        : "+f"((acc)[0]), "+f"((acc)[1]), "+f"((acc)[2]), "+f"((acc)[3])  \
        : "r"((af)[0]), "r"((af)[1]), "r"((af)[2]), "r"((af)[3]),         \
          "r"((bf)[0]), "r"((bf)[1]))
#define CP_ASYNC16(smem_u32, gptr)                                        \
    asm volatile("cp.async.cg.shared.global [%0], [%1], 16;\n"            \
                 :: "r"(smem_u32), "l"(gptr))

// ---------------- kernel 1: FUSED LN(m) + V/G projection — tf32 MMA ----------------
// C (131072 x 512) = LN(m) @ [Wm;Wg]^T, K = 64 in ONE smem pass.
// Phase 1: load raw m tile (128x64) -> smem. Phase 2: LN in-place (2 threads/row).
// Phase 3: load tf32 weights. Phase 4: 4x4x(8 K-steps) MMA. Epilogue unchanged.
// Dynamic smem: As 128x68 + Bs 64x136 = 69632 B.
__global__ void __launch_bounds__(256) k_mproj(const float* __restrict__ m,
                                               const float* __restrict__ lw,
                                               const float* __restrict__ lb,
                                               const float* __restrict__ Wm,
                                               const float* __restrict__ Wg)
{
    extern __shared__ float sm[];
    float* As = sm;             // [128][68]  (stride 68 % 32 == 4 -> conflict-free frags)
    float* Bs = sm + 8704;      // [64][136]
    __shared__ float sSum[256], sSq[256];
    int tid = threadIdx.x;
    int warp = tid >> 5, lane = tid & 31;
    int gid = lane >> 2, tig = lane & 3;
    int warp_m = warp & 1, warp_n = warp >> 1;
    int bx = blockIdx.x, by = blockIdx.y;
    bool isV = (bx < 2);

    // phase 1: raw m tile, 128 rows x 64 cols (2048 float4)
    #pragma unroll
    for (int l = 0; l < 8; l++) {
        int e = tid + l * 256;
        int ar = e >> 4, ac = (e & 15) * 4;
        *(float4*)(&As[ar * 68 + ac]) =
            *(const float4*)(m + (size_t)(by * 128 + ar) * 64 + ac);
    }
    // phase 3 load can overlap: weights -> Bs (tf32)
    {
        int o_local = tid >> 1;
        int k0 = (tid & 1) * 32;
        int o_global = bx * 128 + o_local;
        const float* Wrow = isV ? (Wm + (size_t)o_global * 64)
                                : (Wg + (size_t)(o_global - 256) * 64);
        #pragma unroll
        for (int i = 0; i < 32; i++) Bs[(k0 + i) * 136 + o_local] = to_tf32(Wrow[k0 + i]);
    }
    __syncthreads();

    // phase 2: LN in place. threads tid and tid^128 share row (tid & 127).
    {
        int row = tid & 127;
        int half = tid >> 7;              // 0 or 1
        float s = 0.f, ss = 0.f;
        #pragma unroll
        for (int q = 0; q < 8; q++) {
            float4 v = *(const float4*)(&As[row * 68 + half * 32 + q * 4]);
            s  += v.x + v.y + v.z + v.w;
            ss += v.x*v.x + v.y*v.y + v.z*v.z + v.w*v.w;
        }
        sSum[tid] = s; sSq[tid] = ss;
        __syncthreads();
        float st  = sSum[row] + sSum[row + 128];
        float sst = sSq[row]  + sSq[row + 128];
        float mu   = st * (1.0f / 64.0f);
        float var  = sst * (1.0f / 64.0f) - mu * mu;
        float rinv = rsqrtf(var + 1e-5f);
        #pragma unroll
        for (int q = 0; q < 8; q++) {
            int c = half * 32 + q * 4;
            float4 v = *(const float4*)(&As[row * 68 + c]);
            v.x = to_tf32((v.x - mu) * rinv * lw[c]     + lb[c]);
            v.y = to_tf32((v.y - mu) * rinv * lw[c + 1] + lb[c + 1]);
            v.z = to_tf32((v.z - mu) * rinv * lw[c + 2] + lb[c + 2]);
            v.w = to_tf32((v.w - mu) * rinv * lw[c + 3] + lb[c + 3]);
            *(float4*)(&As[row * 68 + c]) = v;
        }
    }
    __syncthreads();

    // phase 4: MMA over K = 64
    float acc[4][4][4] = {};
    #pragma unroll
    for (int k0 = 0; k0 < 64; k0 += 8) {
        uint32_t af[4][4], bf[4][2];
        #pragma unroll
        for (int mt = 0; mt < 4; mt++) {
            int r0 = warp_m * 64 + mt * 16 + gid;
            af[mt][0] = __float_as_uint(As[ r0      * 68 + k0 + tig]);
            af[mt][1] = __float_as_uint(As[(r0 + 8) * 68 + k0 + tig]);
            af[mt][2] = __float_as_uint(As[ r0      * 68 + k0 + tig + 4]);
            af[mt][3] = __float_as_uint(As[(r0 + 8) * 68 + k0 + tig + 4]);
        }
        #pragma unroll
        for (int nt = 0; nt < 4; nt++) {
            int c = warp_n * 32 + nt * 8 + gid;
            bf[nt][0] = __float_as_uint(Bs[(k0 + tig)     * 136 + c]);
            bf[nt][1] = __float_as_uint(Bs[(k0 + tig + 4) * 136 + c]);
        }
        #pragma unroll
        for (int mt = 0; mt < 4; mt++)
            #pragma unroll
            for (int nt = 0; nt < 4; nt++)
                MMA_TF32(acc[mt][nt], af[mt], bf[nt]);
    }

    // epilogue
    #pragma unroll
    for (int mt = 0; mt < 4; mt++) {
        int rA = by * 128 + warp_m * 64 + mt * 16 + gid;
        #pragma unroll
        for (int nt = 0; nt < 4; nt++) {
            int o = bx * 128 + warp_n * 32 + nt * 8 + 2 * tig;
            #pragma unroll
            for (int half = 0; half < 2; half++) {
                int r = rA + half * 8;
                int s = r >> 9, n = r & 511;
                float c0 = acc[mt][nt][2 * half], c1 = acc[mt][nt][2 * half + 1];
                if (isV) {
                    int h = o >> 5, e = o & 31;
                    size_t t = (size_t)s * 32 + e;
                    d_V[((size_t)h * 8192 + t    ) * 512 + n] = to_tf32(c0);
                    d_V[((size_t)h * 8192 + t + 1) * 512 + n] = to_tf32(c1);
                } else {
                    size_t base = (size_t)r * 256 + (o - 256);
                    *(float2*)(d_G + base) =
                        make_float2(1.0f / (1.0f + expf(-c0)), 1.0f / (1.0f + expf(-c1)));
                }
            }
        }
    }
}

// ---------------- kernel 2: z path -> logits (one warp per (i,j) row) ----------------
__global__ void k_zpath(const float* __restrict__ z, const float* __restrict__ mask,
                        const float* __restrict__ lw, const float* __restrict__ lb,
                        const float* __restrict__ Wz)
{
    __shared__ float sWz[8][128];
    __shared__ float sLw[128], sLb[128];
    int tid = threadIdx.x;
    for (int i = tid; i < 1024; i += 256) sWz[i >> 7][i & 127] = Wz[i];
    if (tid < 128) { sLw[tid] = lw[tid]; sLb[tid] = lb[tid]; }
    __syncthreads();

    int warp = tid >> 5, lane = tid & 31;
    int r = blockIdx.x * 8 + warp;
    const float4 zx = *(const float4*)(z + (size_t)r * 128 + lane * 4);

    float s  = zx.x + zx.y + zx.z + zx.w;
    float ss = zx.x*zx.x + zx.y*zx.y + zx.z*zx.z + zx.w*zx.w;
    s = warpSum(s); ss = warpSum(ss);
    float mu  = s * (1.0f / 128.0f);
    float var = ss * (1.0f / 128.0f) - mu * mu;
    float rinv = rsqrtf(var + 1e-5f);

    float4 w4 = *(const float4*)(sLw + lane * 4);
    float4 b4 = *(const float4*)(sLb + lane * 4);
    float y0 = (zx.x - mu) * rinv * w4.x + b4.x;
    float y1 = (zx.y - mu) * rinv * w4.y + b4.y;
    float y2 = (zx.z - mu) * rinv * w4.z + b4.z;
    float y3 = (zx.w - mu) * rinv * w4.w + b4.w;

    float bias = (1.0f - mask[r]) * (-1000000.0f);
    #pragma unroll
    for (int h = 0; h < 8; h++) {
        float4 wz = *(const float4*)(&sWz[h][lane * 4]);
        float p = y0*wz.x + y1*wz.y + y2*wz.z + y3*wz.w;
        p = warpSum(p);
        if (lane == 0) d_W[(size_t)h * 262144 + r] = p + bias;
    }
}

// ---------------- kernel 3: in-place softmax (tf32-rounded) ----------------
__global__ void k_softmax()
{
    int tid = threadIdx.x, warp = tid >> 5, lane = tid & 31;
    int r = blockIdx.x * 8 + warp;
    float* p = d_W + (size_t)r * 512;
    float v[16];
    float mx = -1e30f;
    #pragma unroll
    for (int u = 0; u < 16; u++) { v[u] = p[u * 32 + lane]; mx = fmaxf(mx, v[u]); }
    mx = warpMax(mx);
    float s = 0.f;
    #pragma unroll
    for (int u = 0; u < 16; u++) { v[u] = expf(v[u] - mx); s += v[u]; }
    s = warpSum(s);
    float inv = 1.0f / s;
    #pragma unroll
    for (int u = 0; u < 16; u++) p[u * 32 + lane] = to_tf32(v[u] * inv);
}

// ---------------- kernel 4: big GEMM — R15 measured-good version (241us) ----------------
// C[i, t] = sum_j w[h][i][j] * V[t][j].  Static 36.9 KB smem, cp.async + wait_group 0,
// 2 resident CTAs/SM provide the latency overlap. DO NOT add intra-CTA pipelining:
// reg-staging, ping-pong, and double-buffer variants all measured neutral-to-worse.
__global__ void __launch_bounds__(256, 2) k_gemm()
{
    __shared__ float As[128 * 36];
    __shared__ float Bs[128 * 36];
    int tid = threadIdx.x;
    int warp = tid >> 5, lane = tid & 31;
    int gid = lane >> 2, tig = lane & 3;
    int warp_m = warp & 1, warp_n = warp >> 1;
    int bx = blockIdx.x, by = blockIdx.y, h = blockIdx.z;
    const float* A  = d_W + (size_t)h * 262144;    // [i][j]
    const float* Bv = d_V + (size_t)h * 4194304;   // [t][j]
    uint32_t sA = (uint32_t)__cvta_generic_to_shared(As);
    uint32_t sB = (uint32_t)__cvta_generic_to_shared(Bs);

    float acc[4][4][4] = {};

    for (int kt = 0; kt < 512; kt += 32) {
        #pragma unroll
        for (int l = 0; l < 4; l++) {
            int e = tid + l * 256;
            int row = e >> 3, kc = (e & 7) * 4;
            CP_ASYNC16(sA + (row * 36 + kc) * 4,
                       A  + (size_t)(by * 128 + row) * 512 + kt + kc);
            CP_ASYNC16(sB + (row * 36 + kc) * 4,
                       Bv + (size_t)(bx * 128 + row) * 512 + kt + kc);
        }
        asm volatile("cp.async.commit_group;\n");
        asm volatile("cp.async.wait_group 0;\n" ::: "memory");
        __syncthreads();

        #pragma unroll
        for (int k0 = 0; k0 < 32; k0 += 8) {
            uint32_t af[4][4], bf[4][2];
            #pragma unroll
            for (int mt = 0; mt < 4; mt++) {
                int r0 = warp_m * 64 + mt * 16 + gid;
                af[mt][0] = __float_as_uint(As[ r0      * 36 + k0 + tig]);
                af[mt][1] = __float_as_uint(As[(r0 + 8) * 36 + k0 + tig]);
                af[mt][2] = __float_as_uint(As[ r0      * 36 + k0 + tig + 4]);
                af[mt][3] = __float_as_uint(As[(r0 + 8) * 36 + k0 + tig + 4]);
            }
            #pragma unroll
            for (int nt = 0; nt < 4; nt++) {
                int c = warp_n * 32 + nt * 8 + gid;
                bf[nt][0] = __float_as_uint(Bs[c * 36 + k0 + tig]);
                bf[nt][1] = __float_as_uint(Bs[c * 36 + k0 + tig + 4]);
            }
            #pragma unroll
            for (int mt = 0; mt < 4; mt++)
                #pragma unroll
                for (int nt = 0; nt < 4; nt++)
                    MMA_TF32(acc[mt][nt], af[mt], bf[nt]);
        }
        __syncthreads();
    }

    #pragma unroll
    for (int mt = 0; mt < 4; mt++) {
        int r0 = by * 128 + warp_m * 64 + mt * 16 + gid;
        #pragma unroll
        for (int nt = 0; nt < 4; nt++) {
            int t = bx * 128 + warp_n * 32 + nt * 8 + 2 * tig;
            int s = t >> 5, e = t & 31;
            size_t b0 = (size_t)r0 * 65536 + (size_t)s * 256 + h * 32 + e;
            size_t b1 = (size_t)(r0 + 8) * 65536 + (size_t)s * 256 + h * 32 + e;
            *(float2*)(d_O + b0) = make_float2(acc[mt][nt][0], acc[mt][nt][1]);
            *(float2*)(d_O + b1) = make_float2(acc[mt][nt][2], acc[mt][nt][3]);
        }
    }
}

// ---------------- kernel 5: gate + output projection — tf32 MMA ----------------
__global__ void __launch_bounds__(256) k_out(float* __restrict__ out,
                                             const float* __restrict__ Wo)
{
    __shared__ float As[128][36];
    __shared__ float Bs[32][72];
    int tid = threadIdx.x;
    int warp = tid >> 5, lane = tid & 31;
    int gid = lane >> 2, tig = lane & 3;
    int warp_m = warp >> 1, warp_n = warp & 1;
    int by = blockIdx.x;

    float acc[2][4][4] = {};
    for (int kt = 0; kt < 256; kt += 32) {
        #pragma unroll
        for (int l = 0; l < 4; l++) {
            int e = tid + l * 256;
            int ar = e >> 3, ac = (e & 7) * 4;
            int r = by * 128 + ar;
            int s = r >> 9, i = r & 511;
            float4 g4 = *(const float4*)(d_G + (size_t)r * 256 + kt + ac);
            float4 o4 = *(const float4*)(d_O + (size_t)i * 65536 + (size_t)s * 256 + kt + ac);
            As[ar][ac]   = to_tf32(g4.x * o4.x);
            As[ar][ac+1] = to_tf32(g4.y * o4.y);
            As[ar][ac+2] = to_tf32(g4.z * o4.z);
            As[ar][ac+3] = to_tf32(g4.w * o4.w);
        }
        {
            int cm = tid >> 2, k0 = (tid & 3) * 8;
            const float* Wrow = Wo + (size_t)cm * 256 + kt + k0;
            #pragma unroll
            for (int i = 0; i < 8; i++) Bs[k0 + i][cm] = to_tf32(Wrow[i]);
        }
        __syncthreads();
        #pragma unroll
        for (int k0 = 0; k0 < 32; k0 += 8) {
            uint32_t af[2][4], bf[4][2];
            #pragma unroll
            for (int mt = 0; mt < 2; mt++) {
                int r0 = warp_m * 32 + mt * 16 + gid;
                af[mt][0] = __float_as_uint(As[r0    ][k0 + tig]);
                af[mt][1] = __float_as_uint(As[r0 + 8][k0 + tig]);
                af[mt][2] = __float_as_uint(As[r0    ][k0 + tig + 4]);
                af[mt][3] = __float_as_uint(As[r0 + 8][k0 + tig + 4]);
            }
            #pragma unroll
            for (int nt = 0; nt < 4; nt++) {
                int c = warp_n * 32 + nt * 8 + gid;
                bf[nt][0] = __float_as_uint(Bs[k0 + tig    ][c]);
                bf[nt][1] = __float_as_uint(Bs[k0 + tig + 4][c]);
            }
            #pragma unroll
            for (int mt = 0; mt < 2; mt++)
                #pragma unroll
                for (int nt = 0; nt < 4; nt++)
                    MMA_TF32(acc[mt][nt], af[mt], bf[nt]);
        }
        __syncthreads();
    }

    #pragma unroll
    for (int mt = 0; mt < 2; mt++) {
        int r0 = by * 128 + warp_m * 32 + mt * 16 + gid;
        #pragma unroll
        for (int nt = 0; nt < 4; nt++) {
            int c = warp_n * 32 + nt * 8 + 2 * tig;
            *(float2*)(out + (size_t)r0 * 64 + c) =
                make_float2(acc[mt][nt][0], acc[mt][nt][1]);
            *(float2*)(out + (size_t)(r0 + 8) * 64 + c) =
                make_float2(acc[mt][nt][2], acc[mt][nt][3]);
        }
    }
}

extern "C" void kernel_launch(void* const* d_in, const int* in_sizes, int n_in,
                              void* d_out, int out_size)
{
    const float *m, *z, *mask, *lmw, *lmb, *lzw, *lzb, *Wm, *Wg, *Wz, *Wo;
    if (n_in > 0 && in_sizes[0] == 8388608) {           // insertion order
        m   = (const float*)d_in[0];  z   = (const float*)d_in[1];
        mask= (const float*)d_in[2];
        lmw = (const float*)d_in[3];  lmb = (const float*)d_in[4];
        lzw = (const float*)d_in[5];  lzb = (const float*)d_in[6];
        Wm  = (const float*)d_in[7];  Wg  = (const float*)d_in[8];
        Wz  = (const float*)d_in[9];  Wo  = (const float*)d_in[10];
    } else {                                            // alphabetical order
        Wg  = (const float*)d_in[0];  Wm  = (const float*)d_in[1];
        Wo  = (const float*)d_in[2];  Wz  = (const float*)d_in[3];
        lmb = (const float*)d_in[4];  lmw = (const float*)d_in[5];
        lzb = (const float*)d_in[6];  lzw = (const float*)d_in[7];
        m   = (const float*)d_in[8];  mask= (const float*)d_in[9];
        z   = (const float*)d_in[10];
    }
    float* out = (float*)d_out;

    const int MPROJ_SMEM = (8704 + 8704) * 4;   // 69632 bytes
    cudaFuncSetAttribute(k_mproj, cudaFuncAttributeMaxDynamicSharedMemorySize, MPROJ_SMEM);

    dim3 gp(4, 1024);
    k_mproj<<<gp, 256, MPROJ_SMEM>>>(m, lmw, lmb, Wm, Wg);   // slot 1 (LN fused)
    k_zpath<<<32768, 256>>>(z, mask, lzw, lzb, Wz);          // slot 2
    k_softmax<<<512, 256>>>();                               // slot 3
    dim3 gg(64, 4, 8);
    k_gemm<<<gg, 256>>>();                                   // slot 4 -> profiled
    k_out<<<1024, 256>>>(out, Wo);                           // slot 5
}